// round 16
// baseline (speedup 1.0000x reference)
#include <cuda_runtime.h>
#include <cuda_fp16.h>
#include <math.h>
#include <stdint.h>

#define NN 50000
#define DD 128
#define HH 8
#define DHH 16
#define EE 800000
#define DFF 512
#define NBLK_SCAN 196   // ceil(50000/256)
#define NTILES 391      // ceil(50000/128)

// ---------------- scratch (static device globals; no allocation) ----------------
__device__ __half    g_zh[NN * DD];              // z, half, row-major
__device__ uint32_t  g_xf[NTILES * 4 * 2048];    // x, A-fragment half layout (K=128)
__device__ uint32_t  g_lnf[NTILES * 4 * 2048];   // LN out, A-fragment (K=128)
__device__ uint32_t  g_intf[NTILES * 16 * 2048]; // FFN inter, A-fragment (K=512)
__device__ uint32_t  g_wtp[4 * 2048];            // W_fc^T, B-fragment [c][2048]
__device__ uint32_t  g_w1p[4 * 4 * 2048];        // W1, B-fragment [c][nt][2048]
__device__ uint32_t  g_w2p[16 * 2048];           // W2, B-fragment [c][2048]
__device__ float g_el[NN * HH];
__device__ float g_er[NN * HH];
__device__ int   g_srcs[EE];
__device__ int   g_rank[EE];
__device__ int   g_deg[NN];
__device__ int   g_base[NN];
__device__ int   g_bsum[256];
__device__ int   g_boff[256];
__device__ float g_hres[NN * DD];

__device__ __forceinline__ uint32_t f2h2(float lo, float hi) {
    __half2 h = __floats2half2_rn(lo, hi);
    return *(uint32_t*)&h;
}

// decode B-frag word index (within 2048-word block) -> (k-pair local, n_local)
__device__ __forceinline__ void bfrag_decode(int rest, int& g, int& pl, int& nloc) {
    int blk = rest >> 6, off = rest & 63;
    g = blk >> 4;
    int u = blk & 15;
    int lw = off >> 1, iw = off & 1;
    pl = (lw & 3) + 4 * iw;
    nloc = u * 8 + (lw >> 2);
}
// decode A-frag word index (within 2048-word block) -> (m_local, k-pair local)
__device__ __forceinline__ void afrag_decode(int off2048, int& m, int& p) {
    int g = off2048 >> 10;
    int off = off2048 & 1023;
    int t4 = off >> 7;
    int r = off & 127;
    int lw = r >> 2, iw = r & 3;
    int mr = (lw >> 2) | ((iw & 1) << 3);
    int pl = (lw & 3) | ((iw >> 1) << 2);
    m = t4 * 16 + mr;
    p = g * 8 + pl;
}

#define XF_WORDS (NTILES * 4 * 2048)

// ---------------- fused prep: zero counters + x->frag + weight frags ----------
__global__ void prep_kernel(const float* __restrict__ x,
                            const float* __restrict__ wfc,
                            const float* __restrict__ W1,
                            const float* __restrict__ W2) {
    int i = blockIdx.x * blockDim.x + threadIdx.x;
    if (i < NN) g_deg[i] = 0;
    if (i < XF_WORDS) {
        int T = i >> 13;
        int r = i & 8191;
        int c = r >> 11;
        int m, p;
        afrag_decode(r & 2047, m, p);
        int row = T * 128 + m;
        int k = c * 32 + 2 * p;
        float v0 = 0.f, v1 = 0.f;
        if (row < NN) {
            float2 v = *(const float2*)&x[(size_t)row * DD + k];
            v0 = v.x; v1 = v.y;
        }
        g_xf[i] = f2h2(v0, v1);
    }
    int j = i - XF_WORDS;
    if (j >= 0 && j < 4 * 2048) {
        int c = j >> 11, rest = j & 2047;
        int g, pl, n;
        bfrag_decode(rest, g, pl, n);
        int k0 = c * 32 + (g * 8 + pl) * 2;
        float v0 = wfc[(n >> 4) * 2048 + k0 * 16 + (n & 15)];
        float v1 = wfc[(n >> 4) * 2048 + (k0 + 1) * 16 + (n & 15)];
        g_wtp[j] = f2h2(v0, v1);
    }
    j -= 4 * 2048;
    if (j >= 0 && j < 4 * 4 * 2048) {
        int c = j >> 13, nt = (j >> 11) & 3, rest = j & 2047;
        int g, pl, nl;
        bfrag_decode(rest, g, pl, nl);
        int n = nt * 128 + nl;
        int k0 = c * 32 + (g * 8 + pl) * 2;
        g_w1p[j] = f2h2(W1[(size_t)k0 * DFF + n], W1[(size_t)(k0 + 1) * DFF + n]);
    }
    j -= 4 * 4 * 2048;
    if (j >= 0 && j < 16 * 2048) {
        int c = j >> 11, rest = j & 2047;
        int g, pl, n;
        bfrag_decode(rest, g, pl, n);
        int k0 = c * 32 + (g * 8 + pl) * 2;
        g_w2p[j] = f2h2(W2[(size_t)k0 * DD + n], W2[(size_t)(k0 + 1) * DD + n]);
    }
}
#define PREP_TOTAL (XF_WORDS + 4 * 2048 + 16 * 2048 + 16 * 2048)

// ---------------- fp16 mma ----------------
__device__ __forceinline__ void mma_f16(float* c, const uint32_t* a, const uint32_t* b) {
    asm volatile(
        "mma.sync.aligned.m16n8k16.row.col.f32.f16.f16.f32 "
        "{%0,%1,%2,%3}, {%4,%5,%6,%7}, {%8,%9}, {%0,%1,%2,%3};"
        : "+f"(c[0]), "+f"(c[1]), "+f"(c[2]), "+f"(c[3])
        : "r"(a[0]), "r"(a[1]), "r"(a[2]), "r"(a[3]), "r"(b[0]), "r"(b[1]));
}

__device__ __forceinline__ void cpa16(uint32_t saddr, const void* gaddr) {
    asm volatile("cp.async.cg.shared.global [%0], [%1], 16;" :: "r"(saddr), "l"(gaddr) : "memory");
}

// ---------------- fp16 tensor GEMM, 128x128 tile, cp.async 3-buffer ------------
// A and B both pre-fragmented in GMEM: A [tileM][chunk][2048], B [chunk][tileN][2048].
// CMODE: 0 = f32 row-major, 1 = half row-major, 2 = half A-fragment for next GEMM
// EPI:   0 plain, 1 relu+bias, 2 bias+res
template <int EPI, int CMODE>
__global__ void __launch_bounds__(256, 2) tgemm_kernel(
    const uint32_t* __restrict__ Afr, const uint32_t* __restrict__ Bp, void* __restrict__ Cv,
    int M, int Nn, int K, const float* __restrict__ bias, const float* __restrict__ res)
{
    __shared__ uint32_t Af[3][2048];
    __shared__ uint32_t Bf[3][2048];

    float* Cf = (float*)Cv;
    __half* Ch = (__half*)Cv;
    uint32_t* Cfr = (uint32_t*)Cv;

    const int tid = threadIdx.x;
    const int lane = tid & 31;
    const int wid = tid >> 5;
    const int wm = wid >> 2;
    const int wn = wid & 3;
    const int m0 = blockIdx.x * 128;
    const int n0 = blockIdx.y * 128;
    const int KC = K >> 5;
    const int NT = Nn >> 7;

    const uint32_t af_addr = (uint32_t)__cvta_generic_to_shared(Af);
    const uint32_t bf_addr = (uint32_t)__cvta_generic_to_shared(Bf);

    auto issue = [&](int c) {
        if (c < KC) {
            int buf = c % 3;
            const uint4* As = (const uint4*)(Afr + ((size_t)blockIdx.x * KC + c) * 2048);
            const uint4* Bs = (const uint4*)(Bp + ((size_t)(c * NT + blockIdx.y)) * 2048);
            uint32_t ad = af_addr + buf * 8192 + 16 * tid;
            uint32_t bd = bf_addr + buf * 8192 + 16 * tid;
            cpa16(ad, As + tid);
            cpa16(ad + 4096, As + tid + 256);
            cpa16(bd, Bs + tid);
            cpa16(bd + 4096, Bs + tid + 256);
        }
        asm volatile("cp.async.commit_group;" ::: "memory");
    };

    float acc[4][4][4];
#pragma unroll
    for (int i = 0; i < 4; ++i)
#pragma unroll
        for (int j = 0; j < 4; ++j)
#pragma unroll
            for (int r = 0; r < 4; ++r) acc[i][j][r] = 0.f;

    auto mma_chunk = [&](int buf) {
#pragma unroll
        for (int g = 0; g < 2; ++g) {
            uint32_t af[4][4], bf[4][2];
#pragma unroll
            for (int mt = 0; mt < 4; ++mt)
                *(uint4*)af[mt] = *(const uint4*)&Af[buf][g * 1024 + (wm * 4 + mt) * 128 + lane * 4];
#pragma unroll
            for (int nt = 0; nt < 4; ++nt)
                *(uint2*)bf[nt] = *(const uint2*)&Bf[buf][((g * 16 + wn * 4 + nt) << 6) + lane * 2];
#pragma unroll
            for (int mt = 0; mt < 4; ++mt)
#pragma unroll
                for (int nt = 0; nt < 4; ++nt)
                    mma_f16(acc[mt][nt], af[mt], bf[nt]);
        }
    };

    issue(0);
    issue(1);
    for (int c = 0; c < KC; ++c) {
        asm volatile("cp.async.wait_group 1;" ::: "memory");
        __syncthreads();
        issue(c + 2);
        mma_chunk(c % 3);
    }

    // epilogue
    const int lr = lane >> 2;
    const int lc = lane & 3;
#pragma unroll
    for (int mt = 0; mt < 4; ++mt) {
#pragma unroll
        for (int nt = 0; nt < 4; ++nt) {
            int row = m0 + wm * 64 + mt * 16 + lr;
            int col = n0 + wn * 32 + nt * 8 + 2 * lc;
            float c0 = acc[mt][nt][0], c1 = acc[mt][nt][1];
            float c2 = acc[mt][nt][2], c3 = acc[mt][nt][3];
            if (EPI == 1) {
                float b0 = bias[col], b1 = bias[col + 1];
                c0 = fmaxf(c0 + b0, 0.f); c1 = fmaxf(c1 + b1, 0.f);
                c2 = fmaxf(c2 + b0, 0.f); c3 = fmaxf(c3 + b1, 0.f);
            }
            if (EPI == 2) {
                float b0 = bias[col], b1 = bias[col + 1];
                if (row < M) {
                    c0 += b0 + res[(size_t)row * Nn + col];
                    c1 += b1 + res[(size_t)row * Nn + col + 1];
                }
                if (row + 8 < M) {
                    c2 += b0 + res[(size_t)(row + 8) * Nn + col];
                    c3 += b1 + res[(size_t)(row + 8) * Nn + col + 1];
                }
            }
            if (CMODE == 0) {
                if (row < M)     *(float2*)&Cf[(size_t)row * Nn + col]       = make_float2(c0, c1);
                if (row + 8 < M) *(float2*)&Cf[(size_t)(row + 8) * Nn + col] = make_float2(c2, c3);
            } else if (CMODE == 1) {
                if (row < M)     *(uint32_t*)&Ch[(size_t)row * Nn + col]       = f2h2(c0, c1);
                if (row + 8 < M) *(uint32_t*)&Ch[(size_t)(row + 8) * Nn + col] = f2h2(c2, c3);
            } else {
                int cc = col >> 5;
                int pw = (col >> 1) & 15;
                int gg = pw >> 3, pl = pw & 7;
                size_t base = ((size_t)blockIdx.x * (Nn >> 5) + cc) * 2048 + gg * 1024;
                int m = row & 127;
                int t4 = m >> 4, mr = m & 15;
                if (row < M)
                    Cfr[base + t4 * 128 + ((mr & 7) * 4 + (pl & 3)) * 4 + ((mr >> 3) + 2 * (pl >> 2))] = f2h2(c0, c1);
                int m2 = m + 8;
                int t42 = m2 >> 4, mr2 = m2 & 15;
                if (row + 8 < M)
                    Cfr[base + t42 * 128 + ((mr2 & 7) * 4 + (pl & 3)) * 4 + ((mr2 >> 3) + 2 * (pl >> 2))] = f2h2(c2, c3);
            }
        }
    }
}

// ---------------- el / er: one thread per (node, head), z half ----------------
__global__ void eler_kernel(const float* __restrict__ a_l, const float* __restrict__ a_r) {
    int idx = blockIdx.x * blockDim.x + threadIdx.x;
    if (idx >= NN * HH) return;
    int n = idx >> 3;
    int h = idx & 7;
    const uint32_t* zw = (const uint32_t*)&g_zh[n * DD + h * DHH];
    uint4 z0 = *(const uint4*)zw;
    uint4 z1 = *(const uint4*)(zw + 4);
    uint32_t w[8] = {z0.x, z0.y, z0.z, z0.w, z1.x, z1.y, z1.z, z1.w};
    const float* lp = &a_l[h * DHH];
    const float* rp = &a_r[h * DHH];
    float pl = 0.f, pr = 0.f;
#pragma unroll
    for (int q = 0; q < 8; ++q) {
        float2 f = __half22float2(*(__half2*)&w[q]);
        pl += f.x * lp[2 * q] + f.y * lp[2 * q + 1];
        pr += f.x * rp[2 * q] + f.y * rp[2 * q + 1];
    }
    g_el[idx] = pl;
    g_er[idx] = pr;
}

// ---------------- degree histogram + per-edge rank ----------------
__global__ void deg_kernel(const int* __restrict__ edst) {
    int e = blockIdx.x * blockDim.x + threadIdx.x;
    if (e >= EE) return;
    g_rank[e] = atomicAdd(&g_deg[edst[e]], 1);
}

// ---------------- scan (2 kernels; block-offset add folded into consumers) -------
__global__ void scan1_kernel() {
    __shared__ int sh[256];
    int t = threadIdx.x;
    int i = blockIdx.x * 256 + t;
    int v = (i < NN) ? g_deg[i] : 0;
    sh[t] = v;
    __syncthreads();
#pragma unroll
    for (int off = 1; off < 256; off <<= 1) {
        int x = (t >= off) ? sh[t - off] : 0;
        __syncthreads();
        sh[t] += x;
        __syncthreads();
    }
    if (i < NN) g_base[i] = sh[t] - v;
    if (t == 255) g_bsum[blockIdx.x] = sh[255];
}
__global__ void scan2_kernel() {
    __shared__ int sh[256];
    int t = threadIdx.x;
    int v = (t < NBLK_SCAN) ? g_bsum[t] : 0;
    sh[t] = v;
    __syncthreads();
#pragma unroll
    for (int off = 1; off < 256; off <<= 1) {
        int x = (t >= off) ? sh[t - off] : 0;
        __syncthreads();
        sh[t] += x;
        __syncthreads();
    }
    g_boff[t] = sh[t] - v;
}

// ---------------- slim scatter: index permute only ----------------
__global__ void scatter_kernel(const int* __restrict__ esrc, const int* __restrict__ edst) {
    int e = blockIdx.x * blockDim.x + threadIdx.x;
    if (e >= EE) return;
    int d = edst[e];
    g_srcs[g_base[d] + g_boff[d >> 8] + g_rank[e]] = esrc[e];
}

// ---------------- aggregation (on-the-fly weights) + elu + residual + LayerNorm --
__global__ void __launch_bounds__(256) agg_ln_kernel(
    const float* __restrict__ x,
    const float* __restrict__ gamma, const float* __restrict__ beta)
{
    __shared__ float sw[8 * 288];
    int warp = threadIdx.x >> 5;
    int lane = threadIdx.x & 31;
    int n = blockIdx.x * 8 + warp;
    if (n >= NN) return;
    float* swp = &sw[warp * 288];
    int start = g_base[n] + g_boff[n >> 8];
    int deg = g_deg[n];
    int h = lane >> 2;

    float4 erv0 = *(const float4*)&g_er[n * HH];
    float4 erv1 = *(const float4*)&g_er[n * HH + 4];
    float er0 = erv0.x, er1 = erv0.y, er2 = erv0.z, er3 = erv0.w;
    float er4 = erv1.x, er5 = erv1.y, er6 = erv1.z, er7 = erv1.w;

    float4 acc = make_float4(0.f, 0.f, 0.f, 0.f);
    float s0 = 0.f, s1 = 0.f, s2 = 0.f, s3 = 0.f;
    float s4 = 0.f, s5 = 0.f, s6 = 0.f, s7 = 0.f;

    for (int b = 0; b < deg; b += 32) {
        int cnt = min(32, deg - b);
        int mysrc = 0;
        if (lane < cnt) {
            mysrc = g_srcs[start + b + lane];
            float4 elv0 = *(const float4*)&g_el[mysrc * HH];
            float4 elv1 = *(const float4*)&g_el[mysrc * HH + 4];
            float v, w;
            v = elv0.x + er0; v = (v > 0.f) ? v : 0.01f * v; w = __expf(v); s0 += w; swp[lane * 9 + 0] = w;
            v = elv0.y + er1; v = (v > 0.f) ? v : 0.01f * v; w = __expf(v); s1 += w; swp[lane * 9 + 1] = w;
            v = elv0.z + er2; v = (v > 0.f) ? v : 0.01f * v; w = __expf(v); s2 += w; swp[lane * 9 + 2] = w;
            v = elv0.w + er3; v = (v > 0.f) ? v : 0.01f * v; w = __expf(v); s3 += w; swp[lane * 9 + 3] = w;
            v = elv1.x + er4; v = (v > 0.f) ? v : 0.01f * v; w = __expf(v); s4 += w; swp[lane * 9 + 4] = w;
            v = elv1.y + er5; v = (v > 0.f) ? v : 0.01f * v; w = __expf(v); s5 += w; swp[lane * 9 + 5] = w;
            v = elv1.z + er6; v = (v > 0.f) ? v : 0.01f * v; w = __expf(v); s6 += w; swp[lane * 9 + 6] = w;
            v = elv1.w + er7; v = (v > 0.f) ? v : 0.01f * v; w = __expf(v); s7 += w; swp[lane * 9 + 7] = w;
        }
        __syncwarp();
#pragma unroll 4
        for (int j = 0; j < cnt; ++j) {
            int src = __shfl_sync(0xffffffffu, mysrc, j);
            float wv = swp[j * 9 + h];
            uint2 zv = *(const uint2*)&g_zh[(size_t)src * DD + lane * 4];
            float2 p0 = __half22float2(*(__half2*)&zv.x);
            float2 p1 = __half22float2(*(__half2*)&zv.y);
            acc.x = fmaf(wv, p0.x, acc.x);
            acc.y = fmaf(wv, p0.y, acc.y);
            acc.z = fmaf(wv, p1.x, acc.z);
            acc.w = fmaf(wv, p1.y, acc.w);
        }
        __syncwarp();
    }
    if (deg > 0) {
#pragma unroll
        for (int o = 16; o >= 1; o >>= 1) {
            s0 += __shfl_xor_sync(0xffffffffu, s0, o);
            s1 += __shfl_xor_sync(0xffffffffu, s1, o);
            s2 += __shfl_xor_sync(0xffffffffu, s2, o);
            s3 += __shfl_xor_sync(0xffffffffu, s3, o);
            s4 += __shfl_xor_sync(0xffffffffu, s4, o);
            s5 += __shfl_xor_sync(0xffffffffu, s5, o);
            s6 += __shfl_xor_sync(0xffffffffu, s6, o);
            s7 += __shfl_xor_sync(0xffffffffu, s7, o);
        }
        float sv;
        switch (h) {
            case 0: sv = s0; break;
            case 1: sv = s1; break;
            case 2: sv = s2; break;
            case 3: sv = s3; break;
            case 4: sv = s4; break;
            case 5: sv = s5; break;
            case 6: sv = s6; break;
            default: sv = s7; break;
        }
        float inv = 1.f / fmaxf(sv, 1e-9f);
        acc.x *= inv; acc.y *= inv; acc.z *= inv; acc.w *= inv;
    }
    float4 xv = ((const float4*)(x + (size_t)n * DD))[lane];
    float4 r;
    r.x = xv.x + (acc.x > 0.f ? acc.x : expm1f(acc.x));
    r.y = xv.y + (acc.y > 0.f ? acc.y : expm1f(acc.y));
    r.z = xv.z + (acc.z > 0.f ? acc.z : expm1f(acc.z));
    r.w = xv.w + (acc.w > 0.f ? acc.w : expm1f(acc.w));
    ((float4*)(g_hres + (size_t)n * DD))[lane] = r;
    float sum = r.x + r.y + r.z + r.w;
    float sq = r.x * r.x + r.y * r.y + r.z * r.z + r.w * r.w;
#pragma unroll
    for (int o = 16; o >= 1; o >>= 1) {
        sum += __shfl_xor_sync(0xffffffffu, sum, o);
        sq  += __shfl_xor_sync(0xffffffffu, sq, o);
    }
    float mu = sum * (1.f / 128.f);
    float var = sq * (1.f / 128.f) - mu * mu;
    float rstd = rsqrtf(var + 1e-5f);
    float4 gv = ((const float4*)gamma)[lane];
    float4 bv = ((const float4*)beta)[lane];
    float o0 = (r.x - mu) * rstd * gv.x + bv.x;
    float o1 = (r.y - mu) * rstd * gv.y + bv.y;
    float o2 = (r.z - mu) * rstd * gv.z + bv.z;
    float o3 = (r.w - mu) * rstd * gv.w + bv.w;
    int T = n >> 7, m = n & 127, t4 = m >> 4, mr = m & 15;
    uint32_t wA = f2h2(o0, o1), wB = f2h2(o2, o3);
    {
        int p = 2 * lane;
        int c = p >> 4, pw = p & 15, g = pw >> 3, pl = pw & 7;
        g_lnf[((size_t)T * 4 + c) * 2048 + g * 1024 + t4 * 128 +
              ((mr & 7) * 4 + (pl & 3)) * 4 + ((mr >> 3) + 2 * (pl >> 2))] = wA;
    }
    {
        int p = 2 * lane + 1;
        int c = p >> 4, pw = p & 15, g = pw >> 3, pl = pw & 7;
        g_lnf[((size_t)T * 4 + c) * 2048 + g * 1024 + t4 * 128 +
              ((mr & 7) * 4 + (pl & 3)) * 4 + ((mr >> 3) + 2 * (pl >> 2))] = wB;
    }
}

// ---------------- launch ----------------
extern "C" void kernel_launch(void* const* d_in, const int* in_sizes, int n_in,
                              void* d_out, int out_size) {
    const float* x      = (const float*)d_in[0];
    const float* wfc    = (const float*)d_in[1];
    const float* a_l    = (const float*)d_in[2];
    const float* a_r    = (const float*)d_in[3];
    const float* gamma  = (const float*)d_in[4];
    const float* beta   = (const float*)d_in[5];
    const float* W1     = (const float*)d_in[6];
    const float* b1     = (const float*)d_in[7];
    const float* W2     = (const float*)d_in[8];
    const float* b2     = (const float*)d_in[9];
    const int* esrc     = (const int*)d_in[10];
    const int* edst     = (const int*)d_in[11];
    float* out          = (float*)d_out;

    void *p_zh, *p_xf, *p_lnf, *p_intf, *p_wtp, *p_w1p, *p_w2p;
    float* p_hres;
    cudaGetSymbolAddress(&p_zh, g_zh);
    cudaGetSymbolAddress(&p_xf, g_xf);
    cudaGetSymbolAddress(&p_lnf, g_lnf);
    cudaGetSymbolAddress(&p_intf, g_intf);
    cudaGetSymbolAddress(&p_wtp, g_wtp);
    cudaGetSymbolAddress(&p_w1p, g_w1p);
    cudaGetSymbolAddress(&p_w2p, g_w2p);
    cudaGetSymbolAddress((void**)&p_hres, g_hres);

    static cudaStream_t s1 = nullptr;
    static cudaEvent_t ev_fork = nullptr, ev_join = nullptr;
    if (s1 == nullptr) {
        cudaStreamCreateWithFlags(&s1, cudaStreamNonBlocking);
        cudaEventCreateWithFlags(&ev_fork, cudaEventDisableTiming);
        cudaEventCreateWithFlags(&ev_join, cudaEventDisableTiming);
    }

    cudaEventRecord(ev_fork, 0);
    cudaStreamWaitEvent(s1, ev_fork, 0);

    prep_kernel<<<(PREP_TOTAL + 255) / 256, 256>>>(x, wfc, W1, W2);     // 1 (main)
    deg_kernel<<<(EE + 255) / 256, 256, 0, s1>>>(edst);                 // 2 (s1)
    scan1_kernel<<<NBLK_SCAN, 256, 0, s1>>>();                          // 3 (s1)

    // z = x @ WT  (A frag, C half row-major)  — launch 4 = profiled slot
    {
        dim3 grid(NTILES, 1);
        tgemm_kernel<0, 1><<<grid, 256>>>((const uint32_t*)p_xf, (const uint32_t*)p_wtp,
                                          p_zh, NN, DD, DD, nullptr, nullptr);
    }
    scan2_kernel<<<1, 256, 0, s1>>>();                                  // 5 (s1)
    scatter_kernel<<<(EE + 255) / 256, 256, 0, s1>>>(esrc, edst);       // 6 (s1)
    eler_kernel<<<(NN * HH + 255) / 256, 256>>>(a_l, a_r);              // 7 (main)

    cudaEventRecord(ev_join, s1);
    cudaStreamWaitEvent(0, ev_join, 0);

    agg_ln_kernel<<<(NN + 7) / 8, 256>>>(x, gamma, beta);               // 8

    // inter = relu(ln @ W1 + b1)  (A frag, C frag for GEMM3)
    {
        dim3 grid(NTILES, DFF / 128);
        tgemm_kernel<1, 2><<<grid, 256>>>((const uint32_t*)p_lnf, (const uint32_t*)p_w1p,
                                          p_intf, NN, DFF, DD, b1, nullptr);
    }
    // out = inter @ W2 + b2 + hres  (A frag, C f32 row-major)
    {
        dim3 grid(NTILES, 1);
        tgemm_kernel<2, 0><<<grid, 256>>>((const uint32_t*)p_intf, (const uint32_t*)p_w2p,
                                          out, NN, DD, DFF, b2, p_hres);
    }
}

// round 17
// speedup vs baseline: 1.0208x; 1.0208x over previous
#include <cuda_runtime.h>
#include <cuda_fp16.h>
#include <math.h>
#include <stdint.h>

#define NN 50000
#define DD 128
#define HH 8
#define DHH 16
#define EE 800000
#define DFF 512
#define NBLK_SCAN 196   // ceil(50000/256)
#define NTILES 391      // ceil(50000/128)

// ---------------- scratch (static device globals; no allocation) ----------------
__device__ __half    g_zh[NN * DD];              // z, half, row-major
__device__ uint32_t  g_xf[NTILES * 4 * 2048];    // x, A-fragment half layout (K=128)
__device__ uint32_t  g_lnf[NTILES * 4 * 2048];   // LN out, A-fragment (K=128)
__device__ uint32_t  g_intf[NTILES * 16 * 2048]; // FFN inter, A-fragment (K=512)
__device__ uint32_t  g_wtp[4 * 2048];            // W_fc^T, B-fragment [c][2048]
__device__ uint32_t  g_w1p[4 * 4 * 2048];        // W1, B-fragment [c][nt][2048]
__device__ uint32_t  g_w2p[16 * 2048];           // W2, B-fragment [c][2048]
__device__ float g_el[NN * HH];
__device__ float g_er[NN * HH];
__device__ int   g_srcs[EE];
__device__ int   g_rank[EE];
__device__ int   g_deg[NN];
__device__ int   g_base[NN];
__device__ int   g_bsum[256];
__device__ int   g_boff[256];
__device__ float g_hres[NN * DD];

__device__ __forceinline__ uint32_t f2h2(float lo, float hi) {
    __half2 h = __floats2half2_rn(lo, hi);
    return *(uint32_t*)&h;
}

// decode B-frag word index (within 2048-word block) -> (k-pair local, n_local)
__device__ __forceinline__ void bfrag_decode(int rest, int& g, int& pl, int& nloc) {
    int blk = rest >> 6, off = rest & 63;
    g = blk >> 4;
    int u = blk & 15;
    int lw = off >> 1, iw = off & 1;
    pl = (lw & 3) + 4 * iw;
    nloc = u * 8 + (lw >> 2);
}
// encode A-frag word address within a tile's [chunk][2048] region, given (m 0..127, pair p 0..15, chunk c)
__device__ __forceinline__ int afrag_encode(int c, int m, int p) {
    int g = p >> 3, pl = p & 7;
    int t4 = m >> 4, mr = m & 15;
    return c * 2048 + g * 1024 + t4 * 128 + ((mr & 7) * 4 + (pl & 3)) * 4 + ((mr >> 3) + 2 * (pl >> 2));
}

#define XQ_THREADS (NN * 32)    // one thread per float4 of x

// ---------------- fused prep: zero counters + x->frag (input-indexed) + weight frags
__global__ void prep_kernel(const float* __restrict__ x,
                            const float* __restrict__ wfc,
                            const float* __restrict__ W1,
                            const float* __restrict__ W2) {
    int i = blockIdx.x * blockDim.x + threadIdx.x;
    if (i < NN) g_deg[i] = 0;
    if (i < XQ_THREADS) {
        int row = i >> 5;
        int q = i & 31;                 // float4 quad -> k = 4q..4q+3, pairs 2q, 2q+1
        float4 v = *(const float4*)&x[(size_t)row * DD + 4 * q];
        int T = row >> 7;
        int m = row & 127;
        int kp0 = 2 * q;                // global pair index 0..63
        uint32_t* base = &g_xf[(size_t)T * 8192];
        base[afrag_encode(kp0 >> 4, m, kp0 & 15)] = f2h2(v.x, v.y);
        int kp1 = kp0 + 1;
        base[afrag_encode(kp1 >> 4, m, kp1 & 15)] = f2h2(v.z, v.w);
    }
    int j = i - XQ_THREADS;
    if (j >= 0 && j < 4 * 2048) {
        int c = j >> 11, rest = j & 2047;
        int g, pl, n;
        bfrag_decode(rest, g, pl, n);
        int k0 = c * 32 + (g * 8 + pl) * 2;
        float v0 = wfc[(n >> 4) * 2048 + k0 * 16 + (n & 15)];
        float v1 = wfc[(n >> 4) * 2048 + (k0 + 1) * 16 + (n & 15)];
        g_wtp[j] = f2h2(v0, v1);
    }
    j -= 4 * 2048;
    if (j >= 0 && j < 4 * 4 * 2048) {
        int c = j >> 13, nt = (j >> 11) & 3, rest = j & 2047;
        int g, pl, nl;
        bfrag_decode(rest, g, pl, nl);
        int n = nt * 128 + nl;
        int k0 = c * 32 + (g * 8 + pl) * 2;
        g_w1p[j] = f2h2(W1[(size_t)k0 * DFF + n], W1[(size_t)(k0 + 1) * DFF + n]);
    }
    j -= 4 * 4 * 2048;
    if (j >= 0 && j < 16 * 2048) {
        int c = j >> 11, rest = j & 2047;
        int g, pl, n;
        bfrag_decode(rest, g, pl, n);
        int k0 = c * 32 + (g * 8 + pl) * 2;
        g_w2p[j] = f2h2(W2[(size_t)k0 * DD + n], W2[(size_t)(k0 + 1) * DD + n]);
    }
}
#define PREP_TOTAL (XQ_THREADS + 4 * 2048 + 16 * 2048 + 16 * 2048)

// ---------------- fp16 mma ----------------
__device__ __forceinline__ void mma_f16(float* c, const uint32_t* a, const uint32_t* b) {
    asm volatile(
        "mma.sync.aligned.m16n8k16.row.col.f32.f16.f16.f32 "
        "{%0,%1,%2,%3}, {%4,%5,%6,%7}, {%8,%9}, {%0,%1,%2,%3};"
        : "+f"(c[0]), "+f"(c[1]), "+f"(c[2]), "+f"(c[3])
        : "r"(a[0]), "r"(a[1]), "r"(a[2]), "r"(a[3]), "r"(b[0]), "r"(b[1]));
}

__device__ __forceinline__ void cpa16(uint32_t saddr, const void* gaddr) {
    asm volatile("cp.async.cg.shared.global [%0], [%1], 16;" :: "r"(saddr), "l"(gaddr) : "memory");
}

// ---------------- fp16 tensor GEMM, 128x128 tile, cp.async 3-buffer ------------
// A and B both pre-fragmented in GMEM: A [tileM][chunk][2048], B [chunk][tileN][2048].
// CMODE: 0 = f32 row-major, 1 = half row-major, 2 = half A-fragment for next GEMM
// EPI:   0 plain, 1 relu+bias, 2 bias+res
template <int EPI, int CMODE>
__global__ void __launch_bounds__(256, 2) tgemm_kernel(
    const uint32_t* __restrict__ Afr, const uint32_t* __restrict__ Bp, void* __restrict__ Cv,
    int M, int Nn, int K, const float* __restrict__ bias, const float* __restrict__ res)
{
    __shared__ uint32_t Af[3][2048];
    __shared__ uint32_t Bf[3][2048];

    float* Cf = (float*)Cv;
    __half* Ch = (__half*)Cv;
    uint32_t* Cfr = (uint32_t*)Cv;

    const int tid = threadIdx.x;
    const int lane = tid & 31;
    const int wid = tid >> 5;
    const int wm = wid >> 2;
    const int wn = wid & 3;
    const int m0 = blockIdx.x * 128;
    const int n0 = blockIdx.y * 128;
    const int KC = K >> 5;
    const int NT = Nn >> 7;

    const uint32_t af_addr = (uint32_t)__cvta_generic_to_shared(Af);
    const uint32_t bf_addr = (uint32_t)__cvta_generic_to_shared(Bf);

    auto issue = [&](int c) {
        if (c < KC) {
            int buf = c % 3;
            const uint4* As = (const uint4*)(Afr + ((size_t)blockIdx.x * KC + c) * 2048);
            const uint4* Bs = (const uint4*)(Bp + ((size_t)(c * NT + blockIdx.y)) * 2048);
            uint32_t ad = af_addr + buf * 8192 + 16 * tid;
            uint32_t bd = bf_addr + buf * 8192 + 16 * tid;
            cpa16(ad, As + tid);
            cpa16(ad + 4096, As + tid + 256);
            cpa16(bd, Bs + tid);
            cpa16(bd + 4096, Bs + tid + 256);
        }
        asm volatile("cp.async.commit_group;" ::: "memory");
    };

    float acc[4][4][4];
#pragma unroll
    for (int i = 0; i < 4; ++i)
#pragma unroll
        for (int j = 0; j < 4; ++j)
#pragma unroll
            for (int r = 0; r < 4; ++r) acc[i][j][r] = 0.f;

    auto mma_chunk = [&](int buf) {
#pragma unroll
        for (int g = 0; g < 2; ++g) {
            uint32_t af[4][4], bf[4][2];
#pragma unroll
            for (int mt = 0; mt < 4; ++mt)
                *(uint4*)af[mt] = *(const uint4*)&Af[buf][g * 1024 + (wm * 4 + mt) * 128 + lane * 4];
#pragma unroll
            for (int nt = 0; nt < 4; ++nt)
                *(uint2*)bf[nt] = *(const uint2*)&Bf[buf][((g * 16 + wn * 4 + nt) << 6) + lane * 2];
#pragma unroll
            for (int mt = 0; mt < 4; ++mt)
#pragma unroll
                for (int nt = 0; nt < 4; ++nt)
                    mma_f16(acc[mt][nt], af[mt], bf[nt]);
        }
    };

    issue(0);
    issue(1);
    for (int c = 0; c < KC; ++c) {
        asm volatile("cp.async.wait_group 1;" ::: "memory");
        __syncthreads();
        issue(c + 2);
        mma_chunk(c % 3);
    }

    // epilogue
    const int lr = lane >> 2;
    const int lc = lane & 3;
#pragma unroll
    for (int mt = 0; mt < 4; ++mt) {
#pragma unroll
        for (int nt = 0; nt < 4; ++nt) {
            int row = m0 + wm * 64 + mt * 16 + lr;
            int col = n0 + wn * 32 + nt * 8 + 2 * lc;
            float c0 = acc[mt][nt][0], c1 = acc[mt][nt][1];
            float c2 = acc[mt][nt][2], c3 = acc[mt][nt][3];
            if (EPI == 1) {
                float b0 = bias[col], b1 = bias[col + 1];
                c0 = fmaxf(c0 + b0, 0.f); c1 = fmaxf(c1 + b1, 0.f);
                c2 = fmaxf(c2 + b0, 0.f); c3 = fmaxf(c3 + b1, 0.f);
            }
            if (EPI == 2) {
                float b0 = bias[col], b1 = bias[col + 1];
                if (row < M) {
                    c0 += b0 + res[(size_t)row * Nn + col];
                    c1 += b1 + res[(size_t)row * Nn + col + 1];
                }
                if (row + 8 < M) {
                    c2 += b0 + res[(size_t)(row + 8) * Nn + col];
                    c3 += b1 + res[(size_t)(row + 8) * Nn + col + 1];
                }
            }
            if (CMODE == 0) {
                if (row < M)     *(float2*)&Cf[(size_t)row * Nn + col]       = make_float2(c0, c1);
                if (row + 8 < M) *(float2*)&Cf[(size_t)(row + 8) * Nn + col] = make_float2(c2, c3);
            } else if (CMODE == 1) {
                if (row < M)     *(uint32_t*)&Ch[(size_t)row * Nn + col]       = f2h2(c0, c1);
                if (row + 8 < M) *(uint32_t*)&Ch[(size_t)(row + 8) * Nn + col] = f2h2(c2, c3);
            } else {
                int cc = col >> 5;
                int pw = (col >> 1) & 15;
                size_t base = ((size_t)blockIdx.x * (Nn >> 5)) * 2048;
                int m = row & 127;
                if (row < M)
                    Cfr[base + afrag_encode(cc, m, pw)] = f2h2(c0, c1);
                if (row + 8 < M)
                    Cfr[base + afrag_encode(cc, m + 8, pw)] = f2h2(c2, c3);
            }
        }
    }
}

// ---------------- el / er: one thread per (node, head), z half ----------------
__global__ void eler_kernel(const float* __restrict__ a_l, const float* __restrict__ a_r) {
    int idx = blockIdx.x * blockDim.x + threadIdx.x;
    if (idx >= NN * HH) return;
    int n = idx >> 3;
    int h = idx & 7;
    const uint32_t* zw = (const uint32_t*)&g_zh[n * DD + h * DHH];
    uint4 z0 = *(const uint4*)zw;
    uint4 z1 = *(const uint4*)(zw + 4);
    uint32_t w[8] = {z0.x, z0.y, z0.z, z0.w, z1.x, z1.y, z1.z, z1.w};
    const float* lp = &a_l[h * DHH];
    const float* rp = &a_r[h * DHH];
    float pl = 0.f, pr = 0.f;
#pragma unroll
    for (int q = 0; q < 8; ++q) {
        float2 f = __half22float2(*(__half2*)&w[q]);
        pl += f.x * lp[2 * q] + f.y * lp[2 * q + 1];
        pr += f.x * rp[2 * q] + f.y * rp[2 * q + 1];
    }
    g_el[idx] = pl;
    g_er[idx] = pr;
}

// ---------------- degree histogram + per-edge rank ----------------
__global__ void deg_kernel(const int* __restrict__ edst) {
    int e = blockIdx.x * blockDim.x + threadIdx.x;
    if (e >= EE) return;
    g_rank[e] = atomicAdd(&g_deg[edst[e]], 1);
}

// ---------------- scan (2 kernels; block-offset add folded into consumers) -------
__global__ void scan1_kernel() {
    __shared__ int sh[256];
    int t = threadIdx.x;
    int i = blockIdx.x * 256 + t;
    int v = (i < NN) ? g_deg[i] : 0;
    sh[t] = v;
    __syncthreads();
#pragma unroll
    for (int off = 1; off < 256; off <<= 1) {
        int x = (t >= off) ? sh[t - off] : 0;
        __syncthreads();
        sh[t] += x;
        __syncthreads();
    }
    if (i < NN) g_base[i] = sh[t] - v;
    if (t == 255) g_bsum[blockIdx.x] = sh[255];
}
__global__ void scan2_kernel() {
    __shared__ int sh[256];
    int t = threadIdx.x;
    int v = (t < NBLK_SCAN) ? g_bsum[t] : 0;
    sh[t] = v;
    __syncthreads();
#pragma unroll
    for (int off = 1; off < 256; off <<= 1) {
        int x = (t >= off) ? sh[t - off] : 0;
        __syncthreads();
        sh[t] += x;
        __syncthreads();
    }
    g_boff[t] = sh[t] - v;
}

// ---------------- slim scatter: index permute only ----------------
__global__ void scatter_kernel(const int* __restrict__ esrc, const int* __restrict__ edst) {
    int e = blockIdx.x * blockDim.x + threadIdx.x;
    if (e >= EE) return;
    int d = edst[e];
    g_srcs[g_base[d] + g_boff[d >> 8] + g_rank[e]] = esrc[e];
}

// ---------------- aggregation (on-the-fly weights) + elu + residual + LayerNorm --
__global__ void __launch_bounds__(256) agg_ln_kernel(
    const float* __restrict__ x,
    const float* __restrict__ gamma, const float* __restrict__ beta)
{
    __shared__ float sw[8 * 288];
    int warp = threadIdx.x >> 5;
    int lane = threadIdx.x & 31;
    int n = blockIdx.x * 8 + warp;
    if (n >= NN) return;
    float* swp = &sw[warp * 288];
    int start = g_base[n] + g_boff[n >> 8];
    int deg = g_deg[n];
    int h = lane >> 2;

    float4 erv0 = *(const float4*)&g_er[n * HH];
    float4 erv1 = *(const float4*)&g_er[n * HH + 4];
    float er0 = erv0.x, er1 = erv0.y, er2 = erv0.z, er3 = erv0.w;
    float er4 = erv1.x, er5 = erv1.y, er6 = erv1.z, er7 = erv1.w;

    float4 acc = make_float4(0.f, 0.f, 0.f, 0.f);
    float s0 = 0.f, s1 = 0.f, s2 = 0.f, s3 = 0.f;
    float s4 = 0.f, s5 = 0.f, s6 = 0.f, s7 = 0.f;

    for (int b = 0; b < deg; b += 32) {
        int cnt = min(32, deg - b);
        int mysrc = 0;
        if (lane < cnt) {
            mysrc = g_srcs[start + b + lane];
            float4 elv0 = *(const float4*)&g_el[mysrc * HH];
            float4 elv1 = *(const float4*)&g_el[mysrc * HH + 4];
            float v, w;
            v = elv0.x + er0; v = (v > 0.f) ? v : 0.01f * v; w = __expf(v); s0 += w; swp[lane * 9 + 0] = w;
            v = elv0.y + er1; v = (v > 0.f) ? v : 0.01f * v; w = __expf(v); s1 += w; swp[lane * 9 + 1] = w;
            v = elv0.z + er2; v = (v > 0.f) ? v : 0.01f * v; w = __expf(v); s2 += w; swp[lane * 9 + 2] = w;
            v = elv0.w + er3; v = (v > 0.f) ? v : 0.01f * v; w = __expf(v); s3 += w; swp[lane * 9 + 3] = w;
            v = elv1.x + er4; v = (v > 0.f) ? v : 0.01f * v; w = __expf(v); s4 += w; swp[lane * 9 + 4] = w;
            v = elv1.y + er5; v = (v > 0.f) ? v : 0.01f * v; w = __expf(v); s5 += w; swp[lane * 9 + 5] = w;
            v = elv1.z + er6; v = (v > 0.f) ? v : 0.01f * v; w = __expf(v); s6 += w; swp[lane * 9 + 6] = w;
            v = elv1.w + er7; v = (v > 0.f) ? v : 0.01f * v; w = __expf(v); s7 += w; swp[lane * 9 + 7] = w;
        }
        __syncwarp();
#pragma unroll 4
        for (int j = 0; j < cnt; ++j) {
            int src = __shfl_sync(0xffffffffu, mysrc, j);
            float wv = swp[j * 9 + h];
            uint2 zv = *(const uint2*)&g_zh[(size_t)src * DD + lane * 4];
            float2 p0 = __half22float2(*(__half2*)&zv.x);
            float2 p1 = __half22float2(*(__half2*)&zv.y);
            acc.x = fmaf(wv, p0.x, acc.x);
            acc.y = fmaf(wv, p0.y, acc.y);
            acc.z = fmaf(wv, p1.x, acc.z);
            acc.w = fmaf(wv, p1.y, acc.w);
        }
        __syncwarp();
    }
    if (deg > 0) {
#pragma unroll
        for (int o = 16; o >= 1; o >>= 1) {
            s0 += __shfl_xor_sync(0xffffffffu, s0, o);
            s1 += __shfl_xor_sync(0xffffffffu, s1, o);
            s2 += __shfl_xor_sync(0xffffffffu, s2, o);
            s3 += __shfl_xor_sync(0xffffffffu, s3, o);
            s4 += __shfl_xor_sync(0xffffffffu, s4, o);
            s5 += __shfl_xor_sync(0xffffffffu, s5, o);
            s6 += __shfl_xor_sync(0xffffffffu, s6, o);
            s7 += __shfl_xor_sync(0xffffffffu, s7, o);
        }
        float sv;
        switch (h) {
            case 0: sv = s0; break;
            case 1: sv = s1; break;
            case 2: sv = s2; break;
            case 3: sv = s3; break;
            case 4: sv = s4; break;
            case 5: sv = s5; break;
            case 6: sv = s6; break;
            default: sv = s7; break;
        }
        float inv = 1.f / fmaxf(sv, 1e-9f);
        acc.x *= inv; acc.y *= inv; acc.z *= inv; acc.w *= inv;
    }
    float4 xv = ((const float4*)(x + (size_t)n * DD))[lane];
    float4 r;
    r.x = xv.x + (acc.x > 0.f ? acc.x : expm1f(acc.x));
    r.y = xv.y + (acc.y > 0.f ? acc.y : expm1f(acc.y));
    r.z = xv.z + (acc.z > 0.f ? acc.z : expm1f(acc.z));
    r.w = xv.w + (acc.w > 0.f ? acc.w : expm1f(acc.w));
    ((float4*)(g_hres + (size_t)n * DD))[lane] = r;
    float sum = r.x + r.y + r.z + r.w;
    float sq = r.x * r.x + r.y * r.y + r.z * r.z + r.w * r.w;
#pragma unroll
    for (int o = 16; o >= 1; o >>= 1) {
        sum += __shfl_xor_sync(0xffffffffu, sum, o);
        sq  += __shfl_xor_sync(0xffffffffu, sq, o);
    }
    float mu = sum * (1.f / 128.f);
    float var = sq * (1.f / 128.f) - mu * mu;
    float rstd = rsqrtf(var + 1e-5f);
    float4 gv = ((const float4*)gamma)[lane];
    float4 bv = ((const float4*)beta)[lane];
    float o0 = (r.x - mu) * rstd * gv.x + bv.x;
    float o1 = (r.y - mu) * rstd * gv.y + bv.y;
    float o2 = (r.z - mu) * rstd * gv.z + bv.z;
    float o3 = (r.w - mu) * rstd * gv.w + bv.w;
    int T = n >> 7, m = n & 127;
    uint32_t* base = &g_lnf[(size_t)T * 8192];
    {
        int p = 2 * lane;
        base[afrag_encode(p >> 4, m, p & 15)] = f2h2(o0, o1);
    }
    {
        int p = 2 * lane + 1;
        base[afrag_encode(p >> 4, m, p & 15)] = f2h2(o2, o3);
    }
}

// ---------------- launch ----------------
extern "C" void kernel_launch(void* const* d_in, const int* in_sizes, int n_in,
                              void* d_out, int out_size) {
    const float* x      = (const float*)d_in[0];
    const float* wfc    = (const float*)d_in[1];
    const float* a_l    = (const float*)d_in[2];
    const float* a_r    = (const float*)d_in[3];
    const float* gamma  = (const float*)d_in[4];
    const float* beta   = (const float*)d_in[5];
    const float* W1     = (const float*)d_in[6];
    const float* b1     = (const float*)d_in[7];
    const float* W2     = (const float*)d_in[8];
    const float* b2     = (const float*)d_in[9];
    const int* esrc     = (const int*)d_in[10];
    const int* edst     = (const int*)d_in[11];
    float* out          = (float*)d_out;

    void *p_zh, *p_xf, *p_lnf, *p_intf, *p_wtp, *p_w1p, *p_w2p;
    float* p_hres;
    cudaGetSymbolAddress(&p_zh, g_zh);
    cudaGetSymbolAddress(&p_xf, g_xf);
    cudaGetSymbolAddress(&p_lnf, g_lnf);
    cudaGetSymbolAddress(&p_intf, g_intf);
    cudaGetSymbolAddress(&p_wtp, g_wtp);
    cudaGetSymbolAddress(&p_w1p, g_w1p);
    cudaGetSymbolAddress(&p_w2p, g_w2p);
    cudaGetSymbolAddress((void**)&p_hres, g_hres);

    static cudaStream_t s1 = nullptr;
    static cudaEvent_t ev_fork = nullptr, ev_join = nullptr;
    if (s1 == nullptr) {
        cudaStreamCreateWithFlags(&s1, cudaStreamNonBlocking);
        cudaEventCreateWithFlags(&ev_fork, cudaEventDisableTiming);
        cudaEventCreateWithFlags(&ev_join, cudaEventDisableTiming);
    }

    cudaEventRecord(ev_fork, 0);
    cudaStreamWaitEvent(s1, ev_fork, 0);

    prep_kernel<<<(PREP_TOTAL + 255) / 256, 256>>>(x, wfc, W1, W2);     // 1 (main)
    deg_kernel<<<(EE + 255) / 256, 256, 0, s1>>>(edst);                 // 2 (s1)
    scan1_kernel<<<NBLK_SCAN, 256, 0, s1>>>();                          // 3 (s1)

    // z = x @ WT  (A frag, C half row-major)  — launch 4 = profiled slot
    {
        dim3 grid(NTILES, 1);
        tgemm_kernel<0, 1><<<grid, 256>>>((const uint32_t*)p_xf, (const uint32_t*)p_wtp,
                                          p_zh, NN, DD, DD, nullptr, nullptr);
    }
    scan2_kernel<<<1, 256, 0, s1>>>();                                  // 5 (s1)
    scatter_kernel<<<(EE + 255) / 256, 256, 0, s1>>>(esrc, edst);       // 6 (s1)
    eler_kernel<<<(NN * HH + 255) / 256, 256>>>(a_l, a_r);              // 7 (main)

    cudaEventRecord(ev_join, s1);
    cudaStreamWaitEvent(0, ev_join, 0);

    agg_ln_kernel<<<(NN + 7) / 8, 256>>>(x, gamma, beta);               // 8

    // inter = relu(ln @ W1 + b1)  (A frag, C frag for GEMM3)
    {
        dim3 grid(NTILES, DFF / 128);
        tgemm_kernel<1, 2><<<grid, 256>>>((const uint32_t*)p_lnf, (const uint32_t*)p_w1p,
                                          p_intf, NN, DFF, DD, b1, nullptr);
    }
    // out = inter @ W2 + b2 + hres  (A frag, C f32 row-major)
    {
        dim3 grid(NTILES, 1);
        tgemm_kernel<2, 0><<<grid, 256>>>((const uint32_t*)p_intf, (const uint32_t*)p_w2p,
                                          out, NN, DD, DFF, b2, p_hres);
    }
}